// round 1
// baseline (speedup 1.0000x reference)
#include <cuda_runtime.h>
#include <math.h>

#define T 256
#define GP 8

#define NB   16
#define NPQ  45
#define NPP  (NPQ*NPQ)      /* 2025 patches per image */
#define NTOT (NB*NPP)       /* 32400 */
#define NBLK (NTOT/GP)      /* 4050 CTAs, exact */

/* shared memory layout (float offsets) */
#define OFF_W1   0                 /* 864   : w1 (3,3,3,32)                  */
#define OFF_W2   864               /* 18432 : w2 (3,3,32,64)                 */
#define OFF_RAW  19296             /* 1536  : 8 patches x 8x8x3              */
#define OFF_RS   20832             /* 6144  : 8 patches x 16x16x3            */
#define OFF_A1   26976             /* 16384 : act1, reused as staging buffer */
#define OFF_A2   43360             /* 8192  : act2                           */
#define OFF_A3   51552             /* 4096  : act3                           */
#define OFF_V    55648             /* 512   : v                              */
#define OFF_BIAS 56160             /* 288 biases + 8 vn2                     */
#define SMEM_FLOATS (56160 + 296)
#define SMEM_BYTES  (SMEM_FLOATS * 4)

__device__ float g_ysum[NB * 128];

__global__ void zero_kernel() {
    for (int i = threadIdx.x; i < NB * 128; i += blockDim.x) g_ysum[i] = 0.f;
}

/* jax.image.resize 'linear' 8->16 stencil: sample = i/2 - 0.25, edge-renormalized */
__device__ __forceinline__ void rtab(int i, int& a0, int& a1, float& w0, float& w1) {
    if (i == 0)       { a0 = 0; a1 = 0; w0 = 1.f;   w1 = 0.f;   }
    else if (i == 15) { a0 = 7; a1 = 7; w0 = 1.f;   w1 = 0.f;   }
    else if (i & 1)   { int m = i >> 1; a0 = m;     a1 = m + 1; w0 = 0.75f; w1 = 0.25f; }
    else              { int m = i >> 1; a0 = m - 1; a1 = m;     w0 = 0.25f; w1 = 0.75f; }
}

__global__ __launch_bounds__(T, 1)
void main_kernel(const float* __restrict__ images,
                 const float* __restrict__ w1, const float* __restrict__ b1,
                 const float* __restrict__ w2, const float* __restrict__ b2,
                 const float* __restrict__ w3, const float* __restrict__ b3,
                 const float* __restrict__ wd, const float* __restrict__ bd,
                 const float* __restrict__ c_x, const float* __restrict__ comp_w,
                 const float* __restrict__ sigma)
{
    extern __shared__ float sm[];
    float* s_w1  = sm + OFF_W1;
    float* s_w2  = sm + OFF_W2;
    float* s_raw = sm + OFF_RAW;
    float* s_rs  = sm + OFF_RS;
    float* s_a1  = sm + OFF_A1;   /* act1 / w3 slice / wd chunk / c_x */
    float* s_a2  = sm + OFF_A2;
    float* s_a3  = sm + OFF_A3;
    float* s_v   = sm + OFF_V;
    float* s_b   = sm + OFF_BIAS;           /* b1[32] b2[64] b3[128] bd[64] */
    float* s_vn2 = sm + OFF_BIAS + 288;

    const int tid = threadIdx.x;
    const int g0  = blockIdx.x * GP;

    /* ---- resident weights + biases ---- */
    for (int i = tid; i < 864;   i += T) s_w1[i] = w1[i];
    for (int i = tid; i < 18432; i += T) s_w2[i] = w2[i];
    if (tid < 32)  s_b[tid]        = b1[tid];
    if (tid < 64)  s_b[32 + tid]   = b2[tid];
    if (tid < 128) s_b[96 + tid]   = b3[tid];
    if (tid < 64)  s_b[224 + tid]  = bd[tid];

    /* ---- raw patch gather: patch (b,py,px), pixel (iy,ix,c) ---- */
    for (int i = tid; i < GP * 192; i += T) {
        int p = i / 192, r = i % 192;
        int iy = r / 24, ix = (r % 24) / 3, c = r % 3;
        int g = g0 + p;
        int b = g / NPP, pp = g % NPP;
        int py = pp / NPQ, px = pp % NPQ;
        s_raw[i] = images[((b * 96 + py * 2 + iy) * 96 + px * 2 + ix) * 3 + c];
    }
    __syncthreads();

    /* ---- bilinear resize 8x8 -> 16x16 ---- */
    for (int i = tid; i < GP * 768; i += T) {
        int p = i / 768, r = i % 768;
        int oy = r / 48, ox = (r % 48) / 3, c = r % 3;
        int ay0, ay1, ax0, ax1; float wy0, wy1, wx0, wx1;
        rtab(oy, ay0, ay1, wy0, wy1);
        rtab(ox, ax0, ax1, wx0, wx1);
        const float* rp = s_raw + p * 192;
        float v00 = rp[(ay0 * 8 + ax0) * 3 + c];
        float v01 = rp[(ay0 * 8 + ax1) * 3 + c];
        float v10 = rp[(ay1 * 8 + ax0) * 3 + c];
        float v11 = rp[(ay1 * 8 + ax1) * 3 + c];
        s_rs[i] = wy0 * (wx0 * v00 + wx1 * v01) + wy1 * (wx0 * v10 + wx1 * v11);
    }
    __syncthreads();

    /* ---- conv1: 16x16x3 -> 8x8x32, stride 2, SAME (pad lo=0 hi=1), relu ---- */
    for (int s = tid; s < GP * 64; s += T) {
        int p = s >> 6, pix = s & 63, oy = pix >> 3, ox = pix & 7;
        float acc[32];
        #pragma unroll
        for (int j = 0; j < 32; j++) acc[j] = 0.f;
        #pragma unroll
        for (int ky = 0; ky < 3; ky++) {
            int iy = 2 * oy + ky; if (iy >= 16) continue;
            #pragma unroll
            for (int kx = 0; kx < 3; kx++) {
                int ix = 2 * ox + kx; if (ix >= 16) continue;
                const float* xin = s_rs + (p * 256 + iy * 16 + ix) * 3;
                #pragma unroll
                for (int ic = 0; ic < 3; ic++) {
                    float xv = xin[ic];
                    const float* wr = s_w1 + ((ky * 3 + kx) * 3 + ic) * 32;
                    #pragma unroll
                    for (int j = 0; j < 32; j++) acc[j] = fmaf(xv, wr[j], acc[j]);
                }
            }
        }
        float* out = s_a1 + (p * 64 + oy * 8 + ox) * 32;
        #pragma unroll
        for (int j = 0; j < 32; j++) out[j] = fmaxf(acc[j] + s_b[j], 0.f);
    }
    __syncthreads();

    /* ---- conv2: 8x8x32 -> 4x4x64, stride 2, SAME, relu. 256 slots exactly ---- */
    {
        int half = tid & 1;
        int slot = tid >> 1;                 /* 0..127 */
        int p = slot >> 4, pix = slot & 15, oy = pix >> 2, ox = pix & 3;
        float acc[32];
        #pragma unroll
        for (int j = 0; j < 32; j++) acc[j] = 0.f;
        #pragma unroll
        for (int ky = 0; ky < 3; ky++) {
            int iy = 2 * oy + ky;
            if (iy < 8) {
                #pragma unroll
                for (int kx = 0; kx < 3; kx++) {
                    int ix = 2 * ox + kx;
                    if (ix < 8) {
                        const float* xin = s_a1 + (p * 64 + iy * 8 + ix) * 32;
                        const float* wb  = s_w2 + (ky * 3 + kx) * 2048 + half * 32;
                        #pragma unroll 4
                        for (int ic = 0; ic < 32; ic++) {
                            float xv = xin[ic];
                            const float* wr = wb + ic * 64;
                            #pragma unroll
                            for (int j = 0; j < 32; j++) acc[j] = fmaf(xv, wr[j], acc[j]);
                        }
                    }
                }
            }
        }
        float* out = s_a2 + (p * 16 + oy * 4 + ox) * 64 + half * 32;
        #pragma unroll
        for (int j = 0; j < 32; j++) out[j] = fmaxf(acc[j] + s_b[32 + half * 32 + j], 0.f);
    }
    __syncthreads();

    /* ---- conv3: 4x4x64 -> 2x2x128, w3 staged per (ky,kx) slice into s_a1 ---- */
    {
        int oct  = tid & 7;                  /* 16-channel group */
        int slot = tid >> 3;                 /* 0..31 */
        int p = slot >> 2, pix = slot & 3, oy = pix >> 1, ox = pix & 1;
        float acc[16];
        #pragma unroll
        for (int j = 0; j < 16; j++) acc[j] = 0.f;
        for (int t9 = 0; t9 < 9; t9++) {
            __syncthreads();
            for (int i = tid; i < 8192; i += T) s_a1[i] = w3[t9 * 8192 + i];
            __syncthreads();
            int ky = t9 / 3, kx = t9 % 3;
            int iy = 2 * oy + ky, ix = 2 * ox + kx;
            if (iy < 4 && ix < 4) {
                const float* xin = s_a2 + (p * 16 + iy * 4 + ix) * 64;
                #pragma unroll 4
                for (int ic = 0; ic < 64; ic++) {
                    float xv = xin[ic];
                    const float* wr = s_a1 + ic * 128 + oct * 16;
                    #pragma unroll
                    for (int j = 0; j < 16; j++) acc[j] = fmaf(xv, wr[j], acc[j]);
                }
            }
        }
        float* out = s_a3 + p * 512 + (oy * 2 + ox) * 128 + oct * 16;
        #pragma unroll
        for (int j = 0; j < 16; j++) out[j] = fmaxf(acc[j] + s_b[96 + oct * 16 + j], 0.f);
    }
    __syncthreads();

    /* ---- dense 512 -> 64, wd staged in 64-row chunks ---- */
    {
        float acc0 = 0.f, acc1 = 0.f;
        int e = tid & 63;
        int p0 = tid >> 6;                   /* 0..3 */
        int p1 = p0 + 4;                     /* slot tid+256 */
        for (int c8 = 0; c8 < 8; c8++) {
            __syncthreads();
            for (int i = tid; i < 4096; i += T) s_a1[i] = wd[c8 * 4096 + i];
            __syncthreads();
            const float* x0 = s_a3 + p0 * 512 + c8 * 64;
            const float* x1 = s_a3 + p1 * 512 + c8 * 64;
            #pragma unroll 8
            for (int i = 0; i < 64; i++) {
                float wv = s_a1[i * 64 + e];
                acc0 = fmaf(x0[i], wv, acc0);
                acc1 = fmaf(x1[i], wv, acc1);
            }
        }
        s_v[p0 * 64 + e] = acc0 + s_b[224 + e];
        s_v[p1 * 64 + e] = acc1 + s_b[224 + e];
    }
    __syncthreads();

    /* ---- ||v||^2, stage c_x ---- */
    if (tid < GP) {
        float a = 0.f;
        for (int ee = 0; ee < 64; ee++) { float x = s_v[tid * 64 + ee]; a = fmaf(x, x, a); }
        s_vn2[tid] = a;
    }
    for (int i = tid; i < 8192; i += T) s_a1[i] = c_x[i];
    __syncthreads();

    /* ---- d2 -> K^2 -> ow -> per-image accumulation ---- */
    float inv_s2 = 1.f / (sigma[0] * sigma[0]);
    for (int s = tid; s < GP * 128; s += T) {
        int p = s >> 7, k = s & 127;
        const float* ck = s_a1 + k * 64;
        const float* vp = s_v  + p * 64;
        float d = s_vn2[p];
        #pragma unroll 8
        for (int ee = 0; ee < 64; ee++) {
            float cv = ck[ee];
            d = fmaf(cv, cv - 2.f * vp[ee], d);   /* c^2 - 2 c v */
        }
        d = fmaxf(d, 0.f);
        float K2  = expf(-d * inv_s2);            /* K^2 = exp(-d2/sigma^2) */
        float owv = fmaxf(comp_w[k] * K2, 1e-10f);
        int b = (g0 + p) / NPP;
        atomicAdd(&g_ysum[b * 128 + k], owv);
    }
}

__global__ void fin_kernel(const float* __restrict__ c_y, float* __restrict__ out) {
    __shared__ float yv2[128 * 10];
    __shared__ float rsum[NB];
    int tid = threadIdx.x;
    for (int k = tid; k < 128; k += blockDim.x) {
        float n2 = 0.f;
        for (int i = 0; i < 10; i++) { float c = c_y[k * 10 + i]; n2 = fmaf(c, c, n2); }
        float inv = 1.f / n2;
        for (int i = 0; i < 10; i++) { float c = c_y[k * 10 + i]; yv2[k * 10 + i] = c * c * inv; }
    }
    if (tid < NB) {
        float s = 0.f;
        for (int k = 0; k < 128; k++) s += g_ysum[tid * 128 + k];
        rsum[tid] = s;
    }
    __syncthreads();
    if (tid < NB * 10) {
        int b = tid / 10, i = tid % 10;
        float a = 0.f;
        for (int k = 0; k < 128; k++) a = fmaf(g_ysum[b * 128 + k], yv2[k * 10 + i], a);
        out[tid] = a / rsum[b];
    }
}

extern "C" void kernel_launch(void* const* d_in, const int* in_sizes, int n_in,
                              void* d_out, int out_size) {
    (void)in_sizes; (void)n_in; (void)out_size;
    const float* images = (const float*)d_in[0];
    const float* w1     = (const float*)d_in[1];
    const float* b1     = (const float*)d_in[2];
    const float* w2     = (const float*)d_in[3];
    const float* b2     = (const float*)d_in[4];
    const float* w3     = (const float*)d_in[5];
    const float* b3     = (const float*)d_in[6];
    const float* wd     = (const float*)d_in[7];
    const float* bd     = (const float*)d_in[8];
    const float* c_x    = (const float*)d_in[9];
    const float* c_y    = (const float*)d_in[10];
    const float* comp_w = (const float*)d_in[11];
    const float* sigma  = (const float*)d_in[12];
    float* out = (float*)d_out;

    cudaFuncSetAttribute(main_kernel, cudaFuncAttributeMaxDynamicSharedMemorySize, SMEM_BYTES);

    zero_kernel<<<1, 256>>>();
    main_kernel<<<NBLK, T, SMEM_BYTES>>>(images, w1, b1, w2, b2, w3, b3,
                                         wd, bd, c_x, comp_w, sigma);
    fin_kernel<<<1, 256>>>(c_y, out);
}

// round 2
// speedup vs baseline: 2.9399x; 2.9399x over previous
#include <cuda_runtime.h>
#include <math.h>

#define T 256
#define GP 8
#define NB   16
#define NPQ  45
#define NPP  (NPQ*NPQ)
#define NTOT (NB*NPP)
#define NBLK (NTOT/GP)      /* 4050 CTAs */

/* float offsets in dynamic smem */
#define OFF_RS    0         /* 6936  : resized, planar [3][8*289] (17x17 pad)   */
#define OFF_ACT1  6936      /* 20736 : [32][8*81] (9x9 pad); reused for w3/wd/cx */
#define OFF_ACT2  27672     /* 12800 : [64][8*25] (5x5 pad)                      */
#define OFF_ACT3  40472     /* 4096  : [p][512] NHWC flat                        */
#define OFF_RAW   44568     /* 1536  : [3][8*64]                                 */
#define OFF_W2S   46104     /* 4096  : w2 tap double buffer 2*2048               */
#define OFF_W1    50200     /* 864                                               */
#define OFF_V     51064     /* 512   : [p][64]                                   */
#define OFF_B     51576     /* 288   : b1 b2 b3 bd                               */
#define OFF_CW    51864     /* 128   : comp_w                                    */
#define OFF_VN2   51992     /* 8                                                 */
#define SMEM_FLOATS 52000
#define SMEM_BYTES  (SMEM_FLOATS * 4)

__device__ float g_ysum[NB * 128];

__global__ void zero_kernel() {
    for (int i = threadIdx.x; i < NB * 128; i += blockDim.x) g_ysum[i] = 0.f;
}

__device__ __forceinline__ void cp16(float* dst, const float* src) {
    unsigned s = (unsigned)__cvta_generic_to_shared(dst);
    asm volatile("cp.async.cg.shared.global [%0], [%1], 16;\n" :: "r"(s), "l"(src));
}
__device__ __forceinline__ void cp_commit() { asm volatile("cp.async.commit_group;\n"); }
__device__ __forceinline__ void cp_wait0()  { asm volatile("cp.async.wait_group 0;\n"); }

/* jax.image.resize 'linear' 8->16: sample i/2-0.25, edge-renormalized */
__device__ __forceinline__ void rtab(int i, int& a0, int& a1, float& w0, float& w1) {
    if (i == 0)       { a0 = 0; a1 = 0; w0 = 1.f;   w1 = 0.f;   }
    else if (i == 15) { a0 = 7; a1 = 7; w0 = 1.f;   w1 = 0.f;   }
    else if (i & 1)   { int m = i >> 1; a0 = m;     a1 = m + 1; w0 = 0.75f; w1 = 0.25f; }
    else              { int m = i >> 1; a0 = m - 1; a1 = m;     w0 = 0.25f; w1 = 0.75f; }
}

__global__ __launch_bounds__(T, 1)
void main_kernel(const float* __restrict__ images,
                 const float* __restrict__ w1, const float* __restrict__ b1,
                 const float* __restrict__ w2, const float* __restrict__ b2,
                 const float* __restrict__ w3, const float* __restrict__ b3,
                 const float* __restrict__ wd, const float* __restrict__ bd,
                 const float* __restrict__ c_x, const float* __restrict__ comp_w,
                 const float* __restrict__ sigma)
{
    extern __shared__ float sm[];
    const int tid = threadIdx.x;
    const int g0  = blockIdx.x * GP;

    float* s_b  = sm + OFF_B;
    float* s_cw = sm + OFF_CW;

    /* ---- init: weights/biases, zero padded act regions, raw gather ---- */
    for (int i = tid; i < 864; i += T) sm[OFF_W1 + i] = w1[i];
    if (tid < 32)  s_b[tid]       = b1[tid];
    if (tid < 64)  s_b[32 + tid]  = b2[tid];
    if (tid < 128) s_b[96 + tid]  = b3[tid];
    if (tid < 64)  s_b[224 + tid] = bd[tid];
    if (tid < 128) s_cw[tid]      = comp_w[tid];
    for (int i = tid; i < OFF_ACT3; i += T) sm[i] = 0.f;   /* rs+act1+act2 */

    for (int i = tid; i < 1536; i += T) {
        int c = i >> 9, rem = i & 511, p = rem >> 6, r = rem & 63;
        int iy = r >> 3, ix = r & 7;
        int g = g0 + p, b = g / NPP, pp = g % NPP;
        int py = pp / NPQ, px = pp % NPQ;
        sm[OFF_RAW + i] = images[((b * 96 + py * 2 + iy) * 96 + px * 2 + ix) * 3 + c];
    }
    __syncthreads();

    /* ---- resize 8x8 -> 16x16 into padded 17x17 planes ---- */
    for (int i = tid; i < 6144; i += T) {
        int c = i >> 11, rem = i & 2047, p = rem >> 8, r = rem & 255;
        int oy = r >> 4, ox = r & 15;
        int ay0, ay1, ax0, ax1; float wy0, wy1, wx0, wx1;
        rtab(oy, ay0, ay1, wy0, wy1);
        rtab(ox, ax0, ax1, wx0, wx1);
        const float* rp = sm + OFF_RAW + c * 512 + p * 64;
        float v00 = rp[ay0 * 8 + ax0], v01 = rp[ay0 * 8 + ax1];
        float v10 = rp[ay1 * 8 + ax0], v11 = rp[ay1 * 8 + ax1];
        sm[OFF_RS + c * 2312 + p * 289 + oy * 17 + ox] =
            wy0 * (wx0 * v00 + wx1 * v01) + wy1 * (wx0 * v10 + wx1 * v11);
    }
    __syncthreads();

    /* ---- conv1: [3][17x17] -> [32][9x9pad], M=512 N=32 K=27, TM=8 TN=8 ---- */
    {
        const int mt = tid >> 2, ng = tid & 3;      /* mt=p*8+oy, ng: 8 ocs */
        const int p = mt >> 3, oy = mt & 7;
        float acc[8][8];
        #pragma unroll
        for (int i = 0; i < 8; i++)
            #pragma unroll
            for (int j = 0; j < 8; j++) acc[i][j] = 0.f;

        #pragma unroll 1
        for (int ky = 0; ky < 3; ky++)
        #pragma unroll 1
        for (int kx = 0; kx < 3; kx++) {
            #pragma unroll
            for (int c = 0; c < 3; c++) {
                const float* ap = sm + OFF_RS + c * 2312 + p * 289 + (2 * oy + ky) * 17 + kx;
                float a[8];
                #pragma unroll
                for (int ox = 0; ox < 8; ox++) a[ox] = ap[2 * ox];
                const float* wp = sm + OFF_W1 + ((ky * 3 + kx) * 3 + c) * 32 + ng * 8;
                float4 bq0 = *(const float4*)(wp);
                float4 bq1 = *(const float4*)(wp + 4);
                float bb[8] = {bq0.x, bq0.y, bq0.z, bq0.w, bq1.x, bq1.y, bq1.z, bq1.w};
                #pragma unroll
                for (int ox = 0; ox < 8; ox++)
                    #pragma unroll
                    for (int j = 0; j < 8; j++)
                        acc[ox][j] = fmaf(a[ox], bb[j], acc[ox][j]);
            }
        }
        #pragma unroll
        for (int j = 0; j < 8; j++) {
            int oc = ng * 8 + j;
            float bias = s_b[oc];
            float* op = sm + OFF_ACT1 + oc * 648 + p * 81 + oy * 9;
            #pragma unroll
            for (int ox = 0; ox < 8; ox++) op[ox] = fmaxf(acc[ox][j] + bias, 0.f);
        }
    }
    __syncthreads();

    /* ---- conv2: [32][9x9] -> [64][5x5pad], M=128 N=64 K=9x32, TM=4 TN=8,
           w2 staged per tap via cp.async double buffer ---- */
    {
        const int mt = tid >> 3, ng = tid & 7;
        const int p = mt >> 2, oy = mt & 3;
        float acc[4][8];
        #pragma unroll
        for (int i = 0; i < 4; i++)
            #pragma unroll
            for (int j = 0; j < 8; j++) acc[i][j] = 0.f;

        /* prologue: stage tap 0 */
        #pragma unroll
        for (int j = 0; j < 2; j++) {
            int i4 = tid + j * 256;
            cp16(sm + OFF_W2S + i4 * 4, w2 + i4 * 4);
        }
        cp_commit();

        #pragma unroll 1
        for (int t = 0; t < 9; t++) {
            cp_wait0();
            __syncthreads();
            if (t < 8) {
                #pragma unroll
                for (int j = 0; j < 2; j++) {
                    int i4 = tid + j * 256;
                    cp16(sm + OFF_W2S + ((t + 1) & 1) * 2048 + i4 * 4,
                         w2 + (t + 1) * 2048 + i4 * 4);
                }
                cp_commit();
            }
            const float* wb = sm + OFF_W2S + (t & 1) * 2048;
            int ky = t / 3, kx = t - ky * 3;
            const float* ap = sm + OFF_ACT1 + p * 81 + (2 * oy + ky) * 9 + kx;
            #pragma unroll 4
            for (int ic = 0; ic < 32; ic++) {
                float a[4];
                #pragma unroll
                for (int ox = 0; ox < 4; ox++) a[ox] = ap[ic * 648 + 2 * ox];
                float4 bq0 = *(const float4*)(wb + ic * 64 + ng * 8);
                float4 bq1 = *(const float4*)(wb + ic * 64 + ng * 8 + 4);
                float bb[8] = {bq0.x, bq0.y, bq0.z, bq0.w, bq1.x, bq1.y, bq1.z, bq1.w};
                #pragma unroll
                for (int ox = 0; ox < 4; ox++)
                    #pragma unroll
                    for (int j = 0; j < 8; j++)
                        acc[ox][j] = fmaf(a[ox], bb[j], acc[ox][j]);
            }
        }
        #pragma unroll
        for (int j = 0; j < 8; j++) {
            int oc = ng * 8 + j;
            float bias = s_b[32 + oc];
            float* op = sm + OFF_ACT2 + oc * 200 + p * 25 + oy * 5;
            #pragma unroll
            for (int ox = 0; ox < 4; ox++) op[ox] = fmaxf(acc[ox][j] + bias, 0.f);
        }
    }
    __syncthreads();

    /* ---- conv3: [64][5x5] -> act3 [p][512], M=32 N=128 K=9x64, TM=4 TN=4,
           w3 tap (8192 f) double-buffered in ACT1 region ---- */
    {
        const int p = tid >> 5, ng = tid & 31;
        float acc[4][4];
        #pragma unroll
        for (int i = 0; i < 4; i++)
            #pragma unroll
            for (int j = 0; j < 4; j++) acc[i][j] = 0.f;

        #pragma unroll
        for (int j = 0; j < 8; j++) {
            int i4 = tid + j * 256;
            cp16(sm + OFF_ACT1 + i4 * 4, w3 + i4 * 4);
        }
        cp_commit();

        #pragma unroll 1
        for (int t = 0; t < 9; t++) {
            cp_wait0();
            __syncthreads();
            if (t < 8) {
                #pragma unroll
                for (int j = 0; j < 8; j++) {
                    int i4 = tid + j * 256;
                    cp16(sm + OFF_ACT1 + ((t + 1) & 1) * 8192 + i4 * 4,
                         w3 + (t + 1) * 8192 + i4 * 4);
                }
                cp_commit();
            }
            const float* wb = sm + OFF_ACT1 + (t & 1) * 8192;
            int ky = t / 3, kx = t - ky * 3;
            const float* ap = sm + OFF_ACT2 + p * 25 + ky * 5 + kx;
            #pragma unroll 4
            for (int ic = 0; ic < 64; ic++) {
                float a[4];
                a[0] = ap[ic * 200];        /* (oy,ox)=(0,0) */
                a[1] = ap[ic * 200 + 2];    /* (0,1) */
                a[2] = ap[ic * 200 + 10];   /* (1,0) */
                a[3] = ap[ic * 200 + 12];   /* (1,1) */
                float4 bq = *(const float4*)(wb + ic * 128 + ng * 4);
                float bb[4] = {bq.x, bq.y, bq.z, bq.w};
                #pragma unroll
                for (int px = 0; px < 4; px++)
                    #pragma unroll
                    for (int j = 0; j < 4; j++)
                        acc[px][j] = fmaf(a[px], bb[j], acc[px][j]);
            }
        }
        #pragma unroll
        for (int j = 0; j < 4; j++) {
            int oc = ng * 4 + j;
            float bias = s_b[96 + oc];
            #pragma unroll
            for (int px = 0; px < 4; px++)
                sm[OFF_ACT3 + p * 512 + px * 128 + oc] = fmaxf(acc[px][j] + bias, 0.f);
        }
    }
    __syncthreads();

    /* ---- dense 512->64, wd chunks (64x64) double-buffered in ACT1 ---- */
    {
        const int p = tid >> 5, lane = tid & 31, e0 = lane * 2;
        float va = 0.f, vb = 0.f;

        #pragma unroll
        for (int j = 0; j < 4; j++) {
            int i4 = tid + j * 256;
            cp16(sm + OFF_ACT1 + i4 * 4, wd + i4 * 4);
        }
        cp_commit();

        #pragma unroll 1
        for (int c = 0; c < 8; c++) {
            cp_wait0();
            __syncthreads();
            if (c < 7) {
                #pragma unroll
                for (int j = 0; j < 4; j++) {
                    int i4 = tid + j * 256;
                    cp16(sm + OFF_ACT1 + ((c + 1) & 1) * 4096 + i4 * 4,
                         wd + (c + 1) * 4096 + i4 * 4);
                }
                cp_commit();
            }
            const float* xp = sm + OFF_ACT3 + p * 512 + c * 64;
            const float* wp = sm + OFF_ACT1 + (c & 1) * 4096;
            #pragma unroll 8
            for (int kk = 0; kk < 64; kk++) {
                float x = xp[kk];
                float2 w = *(const float2*)(wp + kk * 64 + e0);
                va = fmaf(x, w.x, va);
                vb = fmaf(x, w.y, vb);
            }
        }
        sm[OFF_V + p * 64 + e0]     = va + s_b[224 + e0];
        sm[OFF_V + p * 64 + e0 + 1] = vb + s_b[224 + e0 + 1];
    }
    __syncthreads();

    /* ---- head: stage c_x (stride-65 pad), vn2, d2 -> ow -> atomics ---- */
    if (tid < GP) {
        float a = 0.f;
        const float* vp = sm + OFF_V + tid * 64;
        #pragma unroll 8
        for (int e = 0; e < 64; e++) a = fmaf(vp[e], vp[e], a);
        sm[OFF_VN2 + tid] = a;
    }
    for (int i = tid; i < 8192; i += T) {
        int k = i >> 6, e = i & 63;
        sm[OFF_ACT1 + k * 65 + e] = c_x[i];
    }
    __syncthreads();

    {
        float inv_s2 = 1.f / (sigma[0] * sigma[0]);
        int k = tid & 127, pg = tid >> 7;
        float d[4];
        #pragma unroll
        for (int pp = 0; pp < 4; pp++) d[pp] = sm[OFF_VN2 + pg * 4 + pp];
        const float* vp = sm + OFF_V + pg * 256;
        const float* ck = sm + OFF_ACT1 + k * 65;
        #pragma unroll 8
        for (int e = 0; e < 64; e++) {
            float cv = ck[e];
            #pragma unroll
            for (int pp = 0; pp < 4; pp++)
                d[pp] = fmaf(cv, fmaf(-2.f, vp[pp * 64 + e], cv), d[pp]);
        }
        int b0 = (g0 + pg * 4)     / NPP;
        int b3 = (g0 + pg * 4 + 3) / NPP;
        float accA = 0.f, accB = 0.f;
        float cwk = s_cw[k];
        #pragma unroll
        for (int pp = 0; pp < 4; pp++) {
            float dd = fmaxf(d[pp], 0.f);
            float owv = fmaxf(cwk * expf(-dd * inv_s2), 1e-10f);
            int b = (g0 + pg * 4 + pp) / NPP;
            if (b == b0) accA += owv; else accB += owv;
        }
        atomicAdd(&g_ysum[b0 * 128 + k], accA);
        if (b3 != b0) atomicAdd(&g_ysum[b3 * 128 + k], accB);
    }
}

__global__ void fin_kernel(const float* __restrict__ c_y, float* __restrict__ out) {
    __shared__ float yv2[128 * 10];
    __shared__ float rsum[NB];
    int tid = threadIdx.x;
    for (int k = tid; k < 128; k += blockDim.x) {
        float n2 = 0.f;
        for (int i = 0; i < 10; i++) { float c = c_y[k * 10 + i]; n2 = fmaf(c, c, n2); }
        float inv = 1.f / n2;
        for (int i = 0; i < 10; i++) { float c = c_y[k * 10 + i]; yv2[k * 10 + i] = c * c * inv; }
    }
    if (tid < NB) {
        float s = 0.f;
        for (int k = 0; k < 128; k++) s += g_ysum[tid * 128 + k];
        rsum[tid] = s;
    }
    __syncthreads();
    if (tid < NB * 10) {
        int b = tid / 10, i = tid % 10;
        float a = 0.f;
        for (int k = 0; k < 128; k++) a = fmaf(g_ysum[b * 128 + k], yv2[k * 10 + i], a);
        out[tid] = a / rsum[b];
    }
}

extern "C" void kernel_launch(void* const* d_in, const int* in_sizes, int n_in,
                              void* d_out, int out_size) {
    (void)in_sizes; (void)n_in; (void)out_size;
    const float* images = (const float*)d_in[0];
    const float* w1     = (const float*)d_in[1];
    const float* b1     = (const float*)d_in[2];
    const float* w2     = (const float*)d_in[3];
    const float* b2     = (const float*)d_in[4];
    const float* w3     = (const float*)d_in[5];
    const float* b3     = (const float*)d_in[6];
    const float* wd     = (const float*)d_in[7];
    const float* bd     = (const float*)d_in[8];
    const float* c_x    = (const float*)d_in[9];
    const float* c_y    = (const float*)d_in[10];
    const float* comp_w = (const float*)d_in[11];
    const float* sigma  = (const float*)d_in[12];
    float* out = (float*)d_out;

    cudaFuncSetAttribute(main_kernel, cudaFuncAttributeMaxDynamicSharedMemorySize, SMEM_BYTES);

    zero_kernel<<<1, 256>>>();
    main_kernel<<<NBLK, T, SMEM_BYTES>>>(images, w1, b1, w2, b2, w3, b3,
                                         wd, bd, c_x, comp_w, sigma);
    fin_kernel<<<1, 256>>>(c_y, out);
}

// round 3
// speedup vs baseline: 2.9432x; 1.0011x over previous
#include <cuda_runtime.h>
#include <math.h>

#define T 256
#define GP 8
#define NB   16
#define NPQ  45
#define NPP  (NPQ*NPQ)
#define NTOT (NB*NPP)
#define NBLK (NTOT/GP)      /* 4050 CTAs */

/* float offsets in dynamic smem */
#define OFF_RS    0         /* 6936  : resized, planar [3][8*289] (17x17 pad)   */
#define OFF_ACT1  6936      /* 20736 : [32][8*81] (9x9 pad); reused for w3/wd/cx */
#define OFF_ACT2  27672     /* 12800 : [64][8*25] (5x5 pad)                      */
#define OFF_ACT3  40472     /* 4096  : [p][512] NHWC flat                        */
#define OFF_RAW   44568     /* 1536  : [3][8*64]                                 */
#define OFF_W2S   46104     /* 4096  : w2 tap double buffer 2*2048               */
#define OFF_W1    50200     /* 864                                               */
#define OFF_V     51064     /* 512   : [p][64]                                   */
#define OFF_B     51576     /* 288   : b1 b2 b3 bd                               */
#define OFF_CW    51864     /* 128   : comp_w                                    */
#define OFF_VN2   51992     /* 8                                                 */
#define SMEM_FLOATS 52000
#define SMEM_BYTES  (SMEM_FLOATS * 4)

typedef unsigned long long u64;

__device__ float g_ysum[NB * 128];

__global__ void zero_kernel() {
    for (int i = threadIdx.x; i < NB * 128; i += blockDim.x) g_ysum[i] = 0.f;
}

/* ---- packed fp32x2 helpers (Blackwell FFMA2) ---- */
__device__ __forceinline__ u64 pack2(float lo, float hi) {
    u64 r; asm("mov.b64 %0, {%1, %2};" : "=l"(r) : "f"(lo), "f"(hi)); return r;
}
__device__ __forceinline__ void unpack2(u64 v, float& lo, float& hi) {
    asm("mov.b64 {%0, %1}, %2;" : "=f"(lo), "=f"(hi) : "l"(v));
}
__device__ __forceinline__ void fma2(u64& d, u64 a, u64 b) {
    asm("fma.rn.f32x2 %0, %1, %2, %0;" : "+l"(d) : "l"(a), "l"(b));
}

__device__ __forceinline__ void cp16(float* dst, const float* src) {
    unsigned s = (unsigned)__cvta_generic_to_shared(dst);
    asm volatile("cp.async.cg.shared.global [%0], [%1], 16;\n" :: "r"(s), "l"(src));
}
__device__ __forceinline__ void cp_commit() { asm volatile("cp.async.commit_group;\n"); }
__device__ __forceinline__ void cp_wait0()  { asm volatile("cp.async.wait_group 0;\n"); }

/* jax.image.resize 'linear' 8->16: sample i/2-0.25, edge-renormalized */
__device__ __forceinline__ void rtab(int i, int& a0, int& a1, float& w0, float& w1) {
    if (i == 0)       { a0 = 0; a1 = 0; w0 = 1.f;   w1 = 0.f;   }
    else if (i == 15) { a0 = 7; a1 = 7; w0 = 1.f;   w1 = 0.f;   }
    else if (i & 1)   { int m = i >> 1; a0 = m;     a1 = m + 1; w0 = 0.75f; w1 = 0.25f; }
    else              { int m = i >> 1; a0 = m - 1; a1 = m;     w0 = 0.25f; w1 = 0.75f; }
}

__global__ __launch_bounds__(T, 1)
void main_kernel(const float* __restrict__ images,
                 const float* __restrict__ w1, const float* __restrict__ b1,
                 const float* __restrict__ w2, const float* __restrict__ b2,
                 const float* __restrict__ w3, const float* __restrict__ b3,
                 const float* __restrict__ wd, const float* __restrict__ bd,
                 const float* __restrict__ c_x, const float* __restrict__ comp_w,
                 const float* __restrict__ sigma)
{
    extern __shared__ float sm[];
    const int tid = threadIdx.x;
    const int g0  = blockIdx.x * GP;

    float* s_b  = sm + OFF_B;
    float* s_cw = sm + OFF_CW;

    /* ---- init ---- */
    for (int i = tid; i < 864; i += T) sm[OFF_W1 + i] = w1[i];
    if (tid < 32)  s_b[tid]       = b1[tid];
    if (tid < 64)  s_b[32 + tid]  = b2[tid];
    if (tid < 128) s_b[96 + tid]  = b3[tid];
    if (tid < 64)  s_b[224 + tid] = bd[tid];
    if (tid < 128) s_cw[tid]      = comp_w[tid];
    for (int i = tid; i < OFF_ACT3; i += T) sm[i] = 0.f;

    for (int i = tid; i < 1536; i += T) {
        int c = i >> 9, rem = i & 511, p = rem >> 6, r = rem & 63;
        int iy = r >> 3, ix = r & 7;
        int g = g0 + p, b = g / NPP, pp = g % NPP;
        int py = pp / NPQ, px = pp % NPQ;
        sm[OFF_RAW + i] = images[((b * 96 + py * 2 + iy) * 96 + px * 2 + ix) * 3 + c];
    }
    __syncthreads();

    /* ---- resize 8x8 -> 16x16 into padded 17x17 planes ---- */
    for (int i = tid; i < 6144; i += T) {
        int c = i >> 11, rem = i & 2047, p = rem >> 8, r = rem & 255;
        int oy = r >> 4, ox = r & 15;
        int ay0, ay1, ax0, ax1; float wy0, wy1, wx0, wx1;
        rtab(oy, ay0, ay1, wy0, wy1);
        rtab(ox, ax0, ax1, wx0, wx1);
        const float* rp = sm + OFF_RAW + c * 512 + p * 64;
        float v00 = rp[ay0 * 8 + ax0], v01 = rp[ay0 * 8 + ax1];
        float v10 = rp[ay1 * 8 + ax0], v11 = rp[ay1 * 8 + ax1];
        sm[OFF_RS + c * 2312 + p * 289 + oy * 17 + ox] =
            wy0 * (wx0 * v00 + wx1 * v01) + wy1 * (wx0 * v10 + wx1 * v11);
    }
    __syncthreads();

    /* ---- conv1: M=512 N=32 K=27, TM=8, TN=8 (4 packed) ---- */
    {
        const int mt = tid >> 2, ng = tid & 3;
        const int p = mt >> 3, oy = mt & 7;
        u64 acc[8][4];
        #pragma unroll
        for (int i = 0; i < 8; i++)
            #pragma unroll
            for (int j = 0; j < 4; j++) acc[i][j] = 0ull;

        #pragma unroll 1
        for (int ky = 0; ky < 3; ky++)
        #pragma unroll 1
        for (int kx = 0; kx < 3; kx++) {
            #pragma unroll
            for (int c = 0; c < 3; c++) {
                const float* ap = sm + OFF_RS + c * 2312 + p * 289 + (2 * oy + ky) * 17 + kx;
                u64 aa[8];
                #pragma unroll
                for (int ox = 0; ox < 8; ox++) { float av = ap[2 * ox]; aa[ox] = pack2(av, av); }
                const u64* wp2 = (const u64*)(sm + OFF_W1 + ((ky * 3 + kx) * 3 + c) * 32 + ng * 8);
                u64 bb[4] = {wp2[0], wp2[1], wp2[2], wp2[3]};
                #pragma unroll
                for (int ox = 0; ox < 8; ox++)
                    #pragma unroll
                    for (int j = 0; j < 4; j++)
                        fma2(acc[ox][j], aa[ox], bb[j]);
            }
        }
        #pragma unroll
        for (int j = 0; j < 4; j++) {
            int oc0 = ng * 8 + 2 * j;
            float bi0 = s_b[oc0], bi1 = s_b[oc0 + 1];
            float* op0 = sm + OFF_ACT1 + oc0 * 648 + p * 81 + oy * 9;
            float* op1 = op0 + 648;
            #pragma unroll
            for (int ox = 0; ox < 8; ox++) {
                float lo, hi; unpack2(acc[ox][j], lo, hi);
                op0[ox] = fmaxf(lo + bi0, 0.f);
                op1[ox] = fmaxf(hi + bi1, 0.f);
            }
        }
    }
    __syncthreads();

    /* ---- conv2: M=128 N=64 K=288, TM=4, TN=8 (4 packed), per-tap cp.async ---- */
    {
        const int mt = tid >> 3, ng = tid & 7;
        const int p = mt >> 2, oy = mt & 3;
        u64 acc[4][4];
        #pragma unroll
        for (int i = 0; i < 4; i++)
            #pragma unroll
            for (int j = 0; j < 4; j++) acc[i][j] = 0ull;

        #pragma unroll
        for (int j = 0; j < 2; j++) {
            int i4 = tid + j * 256;
            cp16(sm + OFF_W2S + i4 * 4, w2 + i4 * 4);
        }
        cp_commit();

        #pragma unroll 1
        for (int t = 0; t < 9; t++) {
            cp_wait0();
            __syncthreads();
            if (t < 8) {
                #pragma unroll
                for (int j = 0; j < 2; j++) {
                    int i4 = tid + j * 256;
                    cp16(sm + OFF_W2S + ((t + 1) & 1) * 2048 + i4 * 4,
                         w2 + (t + 1) * 2048 + i4 * 4);
                }
                cp_commit();
            }
            const float* wb = sm + OFF_W2S + (t & 1) * 2048;
            int ky = t / 3, kx = t - ky * 3;
            const float* ap = sm + OFF_ACT1 + p * 81 + (2 * oy + ky) * 9 + kx;
            #pragma unroll 8
            for (int ic = 0; ic < 32; ic++) {
                u64 aa[4];
                #pragma unroll
                for (int ox = 0; ox < 4; ox++) { float av = ap[ic * 648 + 2 * ox]; aa[ox] = pack2(av, av); }
                const u64* wp2 = (const u64*)(wb + ic * 64 + ng * 8);
                u64 bb[4] = {wp2[0], wp2[1], wp2[2], wp2[3]};
                #pragma unroll
                for (int ox = 0; ox < 4; ox++)
                    #pragma unroll
                    for (int j = 0; j < 4; j++)
                        fma2(acc[ox][j], aa[ox], bb[j]);
            }
        }
        #pragma unroll
        for (int j = 0; j < 4; j++) {
            int oc0 = ng * 8 + 2 * j;
            float bi0 = s_b[32 + oc0], bi1 = s_b[32 + oc0 + 1];
            float* op0 = sm + OFF_ACT2 + oc0 * 200 + p * 25 + oy * 5;
            float* op1 = op0 + 200;
            #pragma unroll
            for (int ox = 0; ox < 4; ox++) {
                float lo, hi; unpack2(acc[ox][j], lo, hi);
                op0[ox] = fmaxf(lo + bi0, 0.f);
                op1[ox] = fmaxf(hi + bi1, 0.f);
            }
        }
    }
    __syncthreads();

    /* ---- conv3: M=32 N=128 K=576, TM=4, TN=4 (2 packed), w3 double-buffered ---- */
    {
        const int p = tid >> 5, ng = tid & 31;
        u64 acc[4][2];
        #pragma unroll
        for (int i = 0; i < 4; i++) { acc[i][0] = 0ull; acc[i][1] = 0ull; }

        #pragma unroll
        for (int j = 0; j < 8; j++) {
            int i4 = tid + j * 256;
            cp16(sm + OFF_ACT1 + i4 * 4, w3 + i4 * 4);
        }
        cp_commit();

        #pragma unroll 1
        for (int t = 0; t < 9; t++) {
            cp_wait0();
            __syncthreads();
            if (t < 8) {
                #pragma unroll
                for (int j = 0; j < 8; j++) {
                    int i4 = tid + j * 256;
                    cp16(sm + OFF_ACT1 + ((t + 1) & 1) * 8192 + i4 * 4,
                         w3 + (t + 1) * 8192 + i4 * 4);
                }
                cp_commit();
            }
            const float* wb = sm + OFF_ACT1 + (t & 1) * 8192;
            int ky = t / 3, kx = t - ky * 3;
            const float* ap = sm + OFF_ACT2 + p * 25 + ky * 5 + kx;
            #pragma unroll 8
            for (int ic = 0; ic < 64; ic++) {
                float a0 = ap[ic * 200];
                float a1 = ap[ic * 200 + 2];
                float a2 = ap[ic * 200 + 10];
                float a3 = ap[ic * 200 + 12];
                u64 aa[4] = {pack2(a0, a0), pack2(a1, a1), pack2(a2, a2), pack2(a3, a3)};
                const u64* wp2 = (const u64*)(wb + ic * 128 + ng * 4);
                u64 bb0 = wp2[0], bb1 = wp2[1];
                #pragma unroll
                for (int px = 0; px < 4; px++) {
                    fma2(acc[px][0], aa[px], bb0);
                    fma2(acc[px][1], aa[px], bb1);
                }
            }
        }
        #pragma unroll
        for (int j = 0; j < 2; j++) {
            int oc0 = ng * 4 + 2 * j;
            float bi0 = s_b[96 + oc0], bi1 = s_b[96 + oc0 + 1];
            #pragma unroll
            for (int px = 0; px < 4; px++) {
                float lo, hi; unpack2(acc[px][j], lo, hi);
                sm[OFF_ACT3 + p * 512 + px * 128 + oc0]     = fmaxf(lo + bi0, 0.f);
                sm[OFF_ACT3 + p * 512 + px * 128 + oc0 + 1] = fmaxf(hi + bi1, 0.f);
            }
        }
    }
    __syncthreads();

    /* ---- dense 512->64, packed pair per thread ---- */
    {
        const int p = tid >> 5, lane = tid & 31, e0 = lane * 2;
        u64 accp = 0ull;

        #pragma unroll
        for (int j = 0; j < 4; j++) {
            int i4 = tid + j * 256;
            cp16(sm + OFF_ACT1 + i4 * 4, wd + i4 * 4);
        }
        cp_commit();

        #pragma unroll 1
        for (int c = 0; c < 8; c++) {
            cp_wait0();
            __syncthreads();
            if (c < 7) {
                #pragma unroll
                for (int j = 0; j < 4; j++) {
                    int i4 = tid + j * 256;
                    cp16(sm + OFF_ACT1 + ((c + 1) & 1) * 4096 + i4 * 4,
                         wd + (c + 1) * 4096 + i4 * 4);
                }
                cp_commit();
            }
            const float* xp = sm + OFF_ACT3 + p * 512 + c * 64;
            const float* wp = sm + OFF_ACT1 + (c & 1) * 4096;
            #pragma unroll 8
            for (int kk = 0; kk < 64; kk++) {
                float x = xp[kk];
                u64 xx = pack2(x, x);
                u64 w2v = *(const u64*)(wp + kk * 64 + e0);
                fma2(accp, xx, w2v);
            }
        }
        float lo, hi; unpack2(accp, lo, hi);
        sm[OFF_V + p * 64 + e0]     = lo + s_b[224 + e0];
        sm[OFF_V + p * 64 + e0 + 1] = hi + s_b[224 + e0 + 1];
    }
    __syncthreads();

    /* ---- head: stage c_x (stride-65 pad), vn2, d2 -> ow -> atomics ---- */
    if (tid < GP) {
        float a = 0.f;
        const float* vp = sm + OFF_V + tid * 64;
        #pragma unroll 8
        for (int e = 0; e < 64; e++) a = fmaf(vp[e], vp[e], a);
        sm[OFF_VN2 + tid] = a;
    }
    for (int i = tid; i < 8192; i += T) {
        int k = i >> 6, e = i & 63;
        sm[OFF_ACT1 + k * 65 + e] = c_x[i];
    }
    __syncthreads();

    {
        float inv_s2 = 1.f / (sigma[0] * sigma[0]);
        int k = tid & 127, pg = tid >> 7;
        u64 d01 = pack2(sm[OFF_VN2 + pg * 4],     sm[OFF_VN2 + pg * 4 + 1]);
        u64 d23 = pack2(sm[OFF_VN2 + pg * 4 + 2], sm[OFF_VN2 + pg * 4 + 3]);
        const u64 neg2 = pack2(-2.f, -2.f);
        const float* vp = sm + OFF_V + pg * 256;
        const float* ck = sm + OFF_ACT1 + k * 65;
        #pragma unroll 8
        for (int e = 0; e < 64; e++) {
            float cv = ck[e];
            u64 cc = pack2(cv, cv);
            u64 v01 = pack2(vp[e],       vp[64 + e]);
            u64 v23 = pack2(vp[128 + e], vp[192 + e]);
            u64 t01 = cc, t23 = cc;
            fma2(t01, neg2, v01);            /* cv - 2v */
            fma2(t23, neg2, v23);
            fma2(d01, cc, t01);              /* += cv*(cv-2v) */
            fma2(d23, cc, t23);
        }
        float d[4];
        unpack2(d01, d[0], d[1]);
        unpack2(d23, d[2], d[3]);
        int b0 = (g0 + pg * 4)     / NPP;
        int b3 = (g0 + pg * 4 + 3) / NPP;
        float accA = 0.f, accB = 0.f;
        float cwk = s_cw[k];
        #pragma unroll
        for (int pp = 0; pp < 4; pp++) {
            float dd = fmaxf(d[pp], 0.f);
            float owv = fmaxf(cwk * expf(-dd * inv_s2), 1e-10f);
            int b = (g0 + pg * 4 + pp) / NPP;
            if (b == b0) accA += owv; else accB += owv;
        }
        atomicAdd(&g_ysum[b0 * 128 + k], accA);
        if (b3 != b0) atomicAdd(&g_ysum[b3 * 128 + k], accB);
    }
}

__global__ void fin_kernel(const float* __restrict__ c_y, float* __restrict__ out) {
    __shared__ float yv2[128 * 10];
    __shared__ float rsum[NB];
    int tid = threadIdx.x;
    for (int k = tid; k < 128; k += blockDim.x) {
        float n2 = 0.f;
        for (int i = 0; i < 10; i++) { float c = c_y[k * 10 + i]; n2 = fmaf(c, c, n2); }
        float inv = 1.f / n2;
        for (int i = 0; i < 10; i++) { float c = c_y[k * 10 + i]; yv2[k * 10 + i] = c * c * inv; }
    }
    if (tid < NB) {
        float s = 0.f;
        for (int k = 0; k < 128; k++) s += g_ysum[tid * 128 + k];
        rsum[tid] = s;
    }
    __syncthreads();
    if (tid < NB * 10) {
        int b = tid / 10, i = tid % 10;
        float a = 0.f;
        for (int k = 0; k < 128; k++) a = fmaf(g_ysum[b * 128 + k], yv2[k * 10 + i], a);
        out[tid] = a / rsum[b];
    }
}

extern "C" void kernel_launch(void* const* d_in, const int* in_sizes, int n_in,
                              void* d_out, int out_size) {
    (void)in_sizes; (void)n_in; (void)out_size;
    const float* images = (const float*)d_in[0];
    const float* w1     = (const float*)d_in[1];
    const float* b1     = (const float*)d_in[2];
    const float* w2     = (const float*)d_in[3];
    const float* b2     = (const float*)d_in[4];
    const float* w3     = (const float*)d_in[5];
    const float* b3     = (const float*)d_in[6];
    const float* wd     = (const float*)d_in[7];
    const float* bd     = (const float*)d_in[8];
    const float* c_x    = (const float*)d_in[9];
    const float* c_y    = (const float*)d_in[10];
    const float* comp_w = (const float*)d_in[11];
    const float* sigma  = (const float*)d_in[12];
    float* out = (float*)d_out;

    cudaFuncSetAttribute(main_kernel, cudaFuncAttributeMaxDynamicSharedMemorySize, SMEM_BYTES);

    zero_kernel<<<1, 256>>>();
    main_kernel<<<NBLK, T, SMEM_BYTES>>>(images, w1, b1, w2, b2, w3, b3,
                                         wd, bd, c_x, comp_w, sigma);
    fin_kernel<<<1, 256>>>(c_y, out);
}